// round 6
// baseline (speedup 1.0000x reference)
#include <cuda_runtime.h>
#include <cuda_bf16.h>
#include <cstdint>

#define NN 50000
#define EE 1600000
#define GG 512

// ---------------------------------------------------------------------------
// Device scratch (static; no allocations anywhere)
// ---------------------------------------------------------------------------
__device__ int    g_deg[NN];
__device__ int    g_rowptr[NN + 1];
__device__ int    g_fill[NN];
__device__ int    g_col[EE];
__device__ int    g_gstart[GG + 1];
__device__ float4 g_agg4[(size_t)NN * 32];   // [N,128]
__device__ float4 g_h1_4[(size_t)NN * 32];   // [N,128]
__device__ float4 g_h2_4[(size_t)NN * 64];   // [N,256]
__device__ float4 g_y3_4[(size_t)NN * 32];   // [N,128]
__device__ float4 g_z3_4[(size_t)NN * 32];   // [N,128]

__device__ __forceinline__ const float* buf_ptr(int sel, const float* x) {
    switch (sel) {
        case 0: return (const float*)g_agg4;
        case 1: return (const float*)g_h1_4;
        case 2: return (const float*)g_h2_4;
        case 3: return (const float*)g_y3_4;
        case 4: return (const float*)g_z3_4;
        default: return x;
    }
}
__device__ __forceinline__ float* out_ptr(int sel) {
    switch (sel) {
        case 0: return (float*)g_agg4;
        case 1: return (float*)g_h1_4;
        case 2: return (float*)g_h2_4;
        case 3: return (float*)g_y3_4;
        default: return (float*)g_z3_4;
    }
}

// ---------------------------------------------------------------------------
// CSR construction (int32 indices)
// ---------------------------------------------------------------------------
__global__ void zero_deg_kernel() {
    int i = blockIdx.x * blockDim.x + threadIdx.x;
    if (i < NN) g_deg[i] = 0;
}

__global__ void count_kernel(const int* __restrict__ dst) {
    int e = blockIdx.x * blockDim.x + threadIdx.x;
    if (e < EE) {
        int d = dst[e];
        if (d >= 0 && d < NN) atomicAdd(&g_deg[d], 1);
    }
}

__global__ void scan_kernel() {
    __shared__ int wsum[32];
    __shared__ int carry_s;
    int tid = threadIdx.x;
    int lane = tid & 31, wid = tid >> 5;
    if (tid == 0) carry_s = 0;
    __syncthreads();
    for (int base = 0; base < NN; base += 1024) {
        int idx = base + tid;
        int v = (idx < NN) ? g_deg[idx] : 0;
        int sc = v;
        #pragma unroll
        for (int o = 1; o < 32; o <<= 1) {
            int t = __shfl_up_sync(0xFFFFFFFFu, sc, o);
            if (lane >= o) sc += t;
        }
        if (lane == 31) wsum[wid] = sc;
        __syncthreads();
        if (wid == 0) {
            int w = wsum[lane];
            int ws = w;
            #pragma unroll
            for (int o = 1; o < 32; o <<= 1) {
                int t = __shfl_up_sync(0xFFFFFFFFu, ws, o);
                if (lane >= o) ws += t;
            }
            wsum[lane] = ws - w;
        }
        __syncthreads();
        int excl = carry_s + wsum[wid] + sc - v;
        if (idx < NN) {
            g_rowptr[idx] = excl;
            g_fill[idx]   = excl;
        }
        __syncthreads();
        if (tid == 1023) carry_s = excl + v;
        __syncthreads();
    }
    if (threadIdx.x == 0) g_rowptr[NN] = carry_s;
}

__global__ void fill_kernel(const int* __restrict__ src,
                            const int* __restrict__ dst) {
    int e = blockIdx.x * blockDim.x + threadIdx.x;
    if (e < EE) {
        int d = dst[e];
        if (d >= 0 && d < NN) {
            int p = atomicAdd(&g_fill[d], 1);
            g_col[p] = src[e];
        }
    }
}

// ---------------------------------------------------------------------------
// Aggregation: g_agg[n] = sum over in-edges of feat[src], 128 features.
// ---------------------------------------------------------------------------
__global__ void aggregate_kernel(const float* __restrict__ x, int feat_sel) {
    const float* feat = buf_ptr(feat_sel, x);
    int warp = (blockIdx.x * blockDim.x + threadIdx.x) >> 5;
    int lane = threadIdx.x & 31;
    if (warp >= NN) return;
    int s = g_rowptr[warp];
    int e = g_rowptr[warp + 1];
    float4 acc = make_float4(0.f, 0.f, 0.f, 0.f);
    for (int j = s; j < e; j++) {
        int c = g_col[j];
        float4 v = *(const float4*)&feat[(size_t)c * 128 + lane * 4];
        acc.x += v.x; acc.y += v.y; acc.z += v.z; acc.w += v.w;
    }
    g_agg4[(size_t)warp * 32 + lane] = acc;
}

// ---------------------------------------------------------------------------
// tf32 tensor-core GEMM, cp.async double-buffered.
// 128x128 tile, BK=32, 8 warps (4x2), warp tile 32x64 via m16n8k8 tf32 mma.
// Dual-input (A0@W0 + A1@W1) and dual-output (Wb/biasb/cb on blockIdx.y==1).
// ---------------------------------------------------------------------------
__device__ __forceinline__ float to_tf32(float x) {
    float r;
    asm("cvt.rna.tf32.f32 %0, %1;" : "=f"(r) : "f"(x));
    return r;
}
__device__ __forceinline__ uint32_t tf32u(float x) {
    return __float_as_uint(to_tf32(x));
}
__device__ __forceinline__ void mma_tf32(float* c, const uint32_t* a,
                                         const uint32_t* b) {
    asm volatile(
        "mma.sync.aligned.m16n8k8.row.col.f32.tf32.tf32.f32 "
        "{%0,%1,%2,%3}, {%4,%5,%6,%7}, {%8,%9}, {%0,%1,%2,%3};"
        : "+f"(c[0]), "+f"(c[1]), "+f"(c[2]), "+f"(c[3])
        : "r"(a[0]), "r"(a[1]), "r"(a[2]), "r"(a[3]), "r"(b[0]), "r"(b[1]));
}

#define BM 128
#define BN 128
#define BK 32
#define APAD 36
#define BPAD 132
#define SMEM_FLOATS (2 * BM * APAD + 2 * BK * BPAD)

__device__ __forceinline__ void stage_tile(
    const float* __restrict__ A, const float* __restrict__ W,
    int K, int Cout, int kt, int row0, int col0, int M,
    float* Asb, float* Bsb, int tid) {
    #pragma unroll
    for (int i = 0; i < 4; i++) {
        int lin = tid + i * 256;
        int r = lin >> 3, c4 = (lin & 7) << 2;
        int gr = row0 + r;
        const float* src = A + (size_t)gr * K + kt + c4;
        uint32_t dst = (uint32_t)__cvta_generic_to_shared(&Asb[r * APAD + c4]);
        int sz = (gr < M) ? 16 : 0;
        asm volatile("cp.async.ca.shared.global [%0], [%1], 16, %2;\n"
                     :: "r"(dst), "l"(src), "r"(sz));
    }
    #pragma unroll
    for (int i = 0; i < 4; i++) {
        int lin = tid + i * 256;
        int bk = lin >> 5, c4 = (lin & 31) << 2;
        const float* src = W + (size_t)(kt + bk) * Cout + col0 + c4;
        uint32_t dst = (uint32_t)__cvta_generic_to_shared(&Bsb[bk * BPAD + c4]);
        asm volatile("cp.async.ca.shared.global [%0], [%1], 16;\n"
                     :: "r"(dst), "l"(src));
    }
}

__global__ void __launch_bounds__(256)
gemm_tc_kernel(const float* __restrict__ x,
               int a0_sel, const float* __restrict__ W0, int K0,
               int a1_sel, const float* __restrict__ W1, int K1,
               const float* __restrict__ bias, int c_sel,
               int M, int Cout, int relu,
               const float* __restrict__ Wb, const float* __restrict__ biasb,
               int cb_sel) {
    extern __shared__ float smem[];
    float* AsB = smem;                       // 2 x [BM][APAD]
    float* BsB = smem + 2 * BM * APAD;       // 2 x [BK][BPAD]

    int tid  = threadIdx.x;
    int wid  = tid >> 5, lane = tid & 31;
    int gid  = lane >> 2, tig = lane & 3;
    int wm   = wid & 3,  wn  = wid >> 2;
    int row0 = blockIdx.x * BM;
    int col0;
    if (Wb != nullptr) {            // dual-output mode: blockIdx.y picks W/bias/C
        col0 = 0;
        if (blockIdx.y == 1) { W0 = Wb; bias = biasb; c_sel = cb_sel; }
    } else {
        col0 = blockIdx.y * BN;
    }

    float acc[2][8][4];
    #pragma unroll
    for (int i = 0; i < 2; i++)
        #pragma unroll
        for (int j = 0; j < 8; j++)
            #pragma unroll
            for (int k = 0; k < 4; k++) acc[i][j][k] = 0.f;

    const float* A0 = buf_ptr(a0_sel, x);
    const float* A1 = (a1_sel < 0) ? nullptr : buf_ptr(a1_sel, x);
    int T0 = K0 >> 5;
    int T1 = (a1_sel < 0) ? 0 : (K1 >> 5);
    int T  = T0 + T1;

    // prologue: stage tile 0 into buffer 0
    stage_tile(A0, W0, K0, Cout, 0, row0, col0, M, AsB, BsB, tid);
    asm volatile("cp.async.commit_group;\n");

    #pragma unroll 1
    for (int t = 0; t < T; t++) {
        if (t + 1 < T) {
            int tn_ = t + 1;
            const float* A = (tn_ < T0) ? A0 : A1;
            const float* W = (tn_ < T0) ? W0 : W1;
            int K  = (tn_ < T0) ? K0 : K1;
            int kt = (tn_ < T0) ? tn_ * BK : (tn_ - T0) * BK;
            int b  = tn_ & 1;
            stage_tile(A, W, K, Cout, kt, row0, col0, M,
                       AsB + b * BM * APAD, BsB + b * BK * BPAD, tid);
            asm volatile("cp.async.commit_group;\n");
            asm volatile("cp.async.wait_group 1;\n");
        } else {
            asm volatile("cp.async.wait_group 0;\n");
        }
        __syncthreads();

        const float* A_s = AsB + (t & 1) * BM * APAD;
        const float* B_s = BsB + (t & 1) * BK * BPAD;
        #pragma unroll
        for (int ks = 0; ks < 4; ks++) {
            int k0 = ks * 8;
            uint32_t af[2][4];
            #pragma unroll
            for (int mt = 0; mt < 2; mt++) {
                int r = wm * 32 + mt * 16 + gid;
                af[mt][0] = tf32u(A_s[(r    ) * APAD + k0 + tig]);
                af[mt][1] = tf32u(A_s[(r + 8) * APAD + k0 + tig]);
                af[mt][2] = tf32u(A_s[(r    ) * APAD + k0 + tig + 4]);
                af[mt][3] = tf32u(A_s[(r + 8) * APAD + k0 + tig + 4]);
            }
            uint32_t bf[8][2];
            #pragma unroll
            for (int nt = 0; nt < 8; nt++) {
                int c = wn * 64 + nt * 8 + gid;
                bf[nt][0] = tf32u(B_s[(k0 + tig    ) * BPAD + c]);
                bf[nt][1] = tf32u(B_s[(k0 + tig + 4) * BPAD + c]);
            }
            #pragma unroll
            for (int mt = 0; mt < 2; mt++)
                #pragma unroll
                for (int nt = 0; nt < 8; nt++)
                    mma_tf32(acc[mt][nt], af[mt], bf[nt]);
        }
        __syncthreads();
    }

    float* C = out_ptr(c_sel);
    #pragma unroll
    for (int mt = 0; mt < 2; mt++) {
        #pragma unroll
        for (int half = 0; half < 2; half++) {
            int r = row0 + wm * 32 + mt * 16 + gid + half * 8;
            if (r < M) {
                #pragma unroll
                for (int nt = 0; nt < 8; nt++) {
                    int c = col0 + wn * 64 + nt * 8 + tig * 2;
                    float v0 = acc[mt][nt][half * 2 + 0];
                    float v1 = acc[mt][nt][half * 2 + 1];
                    if (bias) { v0 += bias[c]; v1 += bias[c + 1]; }
                    if (relu) { v0 = fmaxf(v0, 0.f); v1 = fmaxf(v1, 0.f); }
                    *(float2*)&C[(size_t)r * Cout + c] = make_float2(v0, v1);
                }
            }
        }
    }
}

// ---------------------------------------------------------------------------
// Graph segment boundaries via binary search over sorted batch (int32)
// ---------------------------------------------------------------------------
__global__ void gstart_kernel(const int* __restrict__ batch) {
    int g = blockIdx.x * blockDim.x + threadIdx.x;
    if (g > GG) return;
    int lo = 0, hi = NN;
    while (lo < hi) {
        int mid = (lo + hi) >> 1;
        if (batch[mid] < g) lo = mid + 1; else hi = mid;
    }
    g_gstart[g] = lo;
}

// ---------------------------------------------------------------------------
// Fused aggregate#3 + mean-pool + MLP head. One 128-thread block per graph.
// pooled[g] = ( sum_{n in g} z3[n]  +  sum_{edges into g} y3[src] ) / cnt_g
// The CSR edge slice of a graph's node range is contiguous, so the gather is
// one flat loop over g_col[rowptr[ns] .. rowptr[ne]).
// ---------------------------------------------------------------------------
__global__ void pool_head_kernel(const float* __restrict__ W1,
                                 const float* __restrict__ b1,
                                 const float* __restrict__ W2,
                                 const float* __restrict__ b2,
                                 float* __restrict__ out) {
    int g = blockIdx.x;
    int c = threadIdx.x;  // 0..127
    int ns = g_gstart[g];
    int ne = g_gstart[g + 1];
    const float* y3 = (const float*)g_y3_4;
    const float* z3 = (const float*)g_z3_4;
    float acc = 0.f;
    for (int n = ns; n < ne; n++)
        acc += z3[(size_t)n * 128 + c];
    int es = g_rowptr[ns];
    int ee = g_rowptr[ne];
    #pragma unroll 4
    for (int j = es; j < ee; j++)
        acc += y3[(size_t)g_col[j] * 128 + c];
    float cnt = (float)((ne - ns) > 1 ? (ne - ns) : 1);
    __shared__ float p[128];
    __shared__ float t[40];
    p[c] = acc / cnt;
    __syncthreads();
    if (c < 40) {
        float tt = b1[c];
        #pragma unroll 4
        for (int k = 0; k < 128; k++) tt += p[k] * W1[k * 40 + c];
        t[c] = tt;
    }
    __syncthreads();
    if (c < 10) {
        float o = b2[c];
        #pragma unroll
        for (int k = 0; k < 40; k++) o += t[k] * W2[k * 10 + c];
        out[g * 10 + c] = o;
    }
}

// ---------------------------------------------------------------------------
// Launch
// ---------------------------------------------------------------------------
extern "C" void kernel_launch(void* const* d_in, const int* in_sizes, int n_in,
                              void* d_out, int out_size) {
    const float* x     = (const float*)d_in[0];
    const int*   ei    = (const int*)d_in[1];
    const int*   batch = (const int*)d_in[2];
    const float* Wr1 = (const float*)d_in[3];
    const float* br1 = (const float*)d_in[4];
    const float* Wo1 = (const float*)d_in[5];
    const float* Wr2 = (const float*)d_in[6];
    const float* br2 = (const float*)d_in[7];
    const float* Wo2 = (const float*)d_in[8];
    const float* Wr3 = (const float*)d_in[9];
    const float* br3 = (const float*)d_in[10];
    const float* Wo3 = (const float*)d_in[11];
    const float* W1  = (const float*)d_in[12];
    const float* b1  = (const float*)d_in[13];
    const float* W2  = (const float*)d_in[14];
    const float* b2  = (const float*)d_in[15];
    float* out = (float*)d_out;

    const int* srcp = ei;
    const int* dstp = ei + EE;

    const int SMEM_BYTES = SMEM_FLOATS * 4;   // 70656
    static bool attr_set = false;
    if (!attr_set) {
        cudaFuncSetAttribute(gemm_tc_kernel,
                             cudaFuncAttributeMaxDynamicSharedMemorySize,
                             SMEM_BYTES);
        attr_set = true;
    }

    const int EB = (EE + 255) / 256;
    const int AGGB = (NN * 32 + 255) / 256;
    dim3 g1((NN + 127) / 128, 1);
    dim3 g2((NN + 127) / 128, 2);

    // CSR build
    zero_deg_kernel<<<(NN + 255) / 256, 256>>>();
    count_kernel<<<EB, 256>>>(dstp);
    scan_kernel<<<1, 1024>>>();
    fill_kernel<<<EB, 256>>>(srcp, dstp);
    gstart_kernel<<<1, 1024>>>(batch);

    // Layer 1: agg = A(x); h1 = relu(agg@Wr1 + x@Wo1 + br1)
    aggregate_kernel<<<AGGB, 256>>>(x, 5);
    gemm_tc_kernel<<<g1, 256, SMEM_BYTES>>>(x, 0, Wr1, 128, 5, Wo1, 128,
                                            br1, 1, NN, 128, 1,
                                            nullptr, nullptr, 0);

    // Layer 2: agg = A(h1); h2 = relu(agg@Wr2 + h1@Wo2 + br2)
    aggregate_kernel<<<AGGB, 256>>>(x, 1);
    gemm_tc_kernel<<<g2, 256, SMEM_BYTES>>>(x, 0, Wr2, 128, 1, Wo2, 128,
                                            br2, 2, NN, 256, 1,
                                            nullptr, nullptr, 0);

    // Layer 3 (matmul-first, dual-output): y3 = h2@Wr3; z3 = h2@Wo3 + br3
    gemm_tc_kernel<<<g2, 256, SMEM_BYTES>>>(x, 2, Wr3, 256, -1, nullptr, 0,
                                            nullptr, 3, NN, 128, 0,
                                            Wo3, br3, 4);

    // Fused aggregate(y3) + mean pool + head
    pool_head_kernel<<<GG, 128>>>(W1, b1, W2, b2, out);
}

// round 7
// speedup vs baseline: 1.6126x; 1.6126x over previous
#include <cuda_runtime.h>
#include <cuda_bf16.h>
#include <cstdint>

#define NN 50000
#define EE 1600000
#define GG 512

// ---------------------------------------------------------------------------
// Device scratch (static; no allocations anywhere)
// ---------------------------------------------------------------------------
__device__ int    g_deg[NN];
__device__ int    g_rowptr[NN + 1];
__device__ int    g_fill[NN];
__device__ int    g_col[EE];
__device__ int    g_gstart[GG + 1];
__device__ float4 g_agg4[(size_t)NN * 32];   // [N,128]
__device__ float4 g_h1_4[(size_t)NN * 32];   // [N,128]
__device__ float4 g_h2_4[(size_t)NN * 64];   // [N,256]
__device__ float4 g_y3_4[(size_t)NN * 32];   // [N,128]
__device__ float4 g_z3_4[(size_t)NN * 32];   // [N,128]

__device__ __forceinline__ const float* buf_ptr(int sel, const float* x) {
    switch (sel) {
        case 0: return (const float*)g_agg4;
        case 1: return (const float*)g_h1_4;
        case 2: return (const float*)g_h2_4;
        case 3: return (const float*)g_y3_4;
        case 4: return (const float*)g_z3_4;
        default: return x;
    }
}
__device__ __forceinline__ float* out_ptr(int sel) {
    switch (sel) {
        case 0: return (float*)g_agg4;
        case 1: return (float*)g_h1_4;
        case 2: return (float*)g_h2_4;
        case 3: return (float*)g_y3_4;
        default: return (float*)g_z3_4;
    }
}

// ---------------------------------------------------------------------------
// CSR construction (int32 indices)
// ---------------------------------------------------------------------------
__global__ void zero_deg_kernel() {
    int i = blockIdx.x * blockDim.x + threadIdx.x;
    if (i < NN) g_deg[i] = 0;
}

__global__ void count_kernel(const int* __restrict__ dst) {
    int e = blockIdx.x * blockDim.x + threadIdx.x;
    if (e < EE) {
        int d = dst[e];
        if (d >= 0 && d < NN) atomicAdd(&g_deg[d], 1);
    }
}

__global__ void scan_kernel() {
    __shared__ int wsum[32];
    __shared__ int carry_s;
    int tid = threadIdx.x;
    int lane = tid & 31, wid = tid >> 5;
    if (tid == 0) carry_s = 0;
    __syncthreads();
    for (int base = 0; base < NN; base += 1024) {
        int idx = base + tid;
        int v = (idx < NN) ? g_deg[idx] : 0;
        int sc = v;
        #pragma unroll
        for (int o = 1; o < 32; o <<= 1) {
            int t = __shfl_up_sync(0xFFFFFFFFu, sc, o);
            if (lane >= o) sc += t;
        }
        if (lane == 31) wsum[wid] = sc;
        __syncthreads();
        if (wid == 0) {
            int w = wsum[lane];
            int ws = w;
            #pragma unroll
            for (int o = 1; o < 32; o <<= 1) {
                int t = __shfl_up_sync(0xFFFFFFFFu, ws, o);
                if (lane >= o) ws += t;
            }
            wsum[lane] = ws - w;
        }
        __syncthreads();
        int excl = carry_s + wsum[wid] + sc - v;
        if (idx < NN) {
            g_rowptr[idx] = excl;
            g_fill[idx]   = excl;
        }
        __syncthreads();
        if (tid == 1023) carry_s = excl + v;
        __syncthreads();
    }
    if (threadIdx.x == 0) g_rowptr[NN] = carry_s;
}

__global__ void fill_kernel(const int* __restrict__ src,
                            const int* __restrict__ dst) {
    int e = blockIdx.x * blockDim.x + threadIdx.x;
    if (e < EE) {
        int d = dst[e];
        if (d >= 0 && d < NN) {
            int p = atomicAdd(&g_fill[d], 1);
            g_col[p] = src[e];
        }
    }
}

// ---------------------------------------------------------------------------
// Aggregation: g_agg[n] = sum over in-edges of feat[src], 128 features.
// One warp per node, float4 per lane. 50K warps — saturates LTS.
// ---------------------------------------------------------------------------
__global__ void aggregate_kernel(const float* __restrict__ x, int feat_sel) {
    const float* feat = buf_ptr(feat_sel, x);
    int warp = (blockIdx.x * blockDim.x + threadIdx.x) >> 5;
    int lane = threadIdx.x & 31;
    if (warp >= NN) return;
    int s = g_rowptr[warp];
    int e = g_rowptr[warp + 1];
    float4 acc = make_float4(0.f, 0.f, 0.f, 0.f);
    for (int j = s; j < e; j++) {
        int c = g_col[j];
        float4 v = *(const float4*)&feat[(size_t)c * 128 + lane * 4];
        acc.x += v.x; acc.y += v.y; acc.z += v.z; acc.w += v.w;
    }
    g_agg4[(size_t)warp * 32 + lane] = acc;
}

// ---------------------------------------------------------------------------
// tf32 tensor-core GEMM with register-prefetch double buffering.
// 128x128 tile, BK=32, 8 warps (4x2), warp tile 32x64 via m16n8k8 tf32 mma.
// cvt.rna at staging time (off the inner loop). Static smem, 2 CTAs/SM.
// Dual-input (A0@W0 + A1@W1); dual-output (Wb/biasb/cb on blockIdx.y==1).
// ---------------------------------------------------------------------------
__device__ __forceinline__ float to_tf32(float x) {
    float r;
    asm("cvt.rna.tf32.f32 %0, %1;" : "=f"(r) : "f"(x));
    return r;
}
__device__ __forceinline__ void mma_tf32(float* c, const uint32_t* a,
                                         const uint32_t* b) {
    asm volatile(
        "mma.sync.aligned.m16n8k8.row.col.f32.tf32.tf32.f32 "
        "{%0,%1,%2,%3}, {%4,%5,%6,%7}, {%8,%9}, {%0,%1,%2,%3};"
        : "+f"(c[0]), "+f"(c[1]), "+f"(c[2]), "+f"(c[3])
        : "r"(a[0]), "r"(a[1]), "r"(a[2]), "r"(a[3]), "r"(b[0]), "r"(b[1]));
}

#define BM 128
#define BN 128
#define BK 32

__device__ __forceinline__ void ldg_tile(
    const float* __restrict__ A, const float* __restrict__ W,
    int K, int Cout, int kt, int row0, int col0, int M, int tid,
    float4* Ar, float4* Br) {
    #pragma unroll
    for (int i = 0; i < 4; i++) {
        int lin = tid + i * 256;
        int r = lin >> 3, c4 = (lin & 7) << 2;
        int gr = row0 + r;
        Ar[i] = (gr < M) ? *(const float4*)&A[(size_t)gr * K + kt + c4]
                         : make_float4(0.f, 0.f, 0.f, 0.f);
    }
    #pragma unroll
    for (int i = 0; i < 4; i++) {
        int lin = tid + i * 256;
        int bk = lin >> 5, c4 = (lin & 31) << 2;
        Br[i] = *(const float4*)&W[(size_t)(kt + bk) * Cout + col0 + c4];
    }
}

__global__ void __launch_bounds__(256, 2)
gemm_tc_kernel(const float* __restrict__ x,
               int a0_sel, const float* __restrict__ W0, int K0,
               int a1_sel, const float* __restrict__ W1, int K1,
               const float* __restrict__ bias, int c_sel,
               int M, int Cout, int relu,
               const float* __restrict__ Wb, const float* __restrict__ biasb,
               int cb_sel) {
    __shared__ float As[BM][BK + 4];   // 36-float rows
    __shared__ float Bs[BK][BN + 8];   // 136-float rows

    int tid  = threadIdx.x;
    int wid  = tid >> 5, lane = tid & 31;
    int gid  = lane >> 2, tig = lane & 3;
    int wm   = wid & 3,  wn  = wid >> 2;
    int row0 = blockIdx.x * BM;
    int col0;
    if (Wb != nullptr) {             // dual-output: blockIdx.y picks W/bias/C
        col0 = 0;
        if (blockIdx.y == 1) { W0 = Wb; bias = biasb; c_sel = cb_sel; }
    } else {
        col0 = blockIdx.y * BN;
    }

    float acc[2][8][4];
    #pragma unroll
    for (int i = 0; i < 2; i++)
        #pragma unroll
        for (int j = 0; j < 8; j++)
            #pragma unroll
            for (int k = 0; k < 4; k++) acc[i][j][k] = 0.f;

    const float* A0 = buf_ptr(a0_sel, x);
    const float* A1 = (a1_sel < 0) ? nullptr : buf_ptr(a1_sel, x);
    int T0 = K0 >> 5;
    int T1 = (a1_sel < 0) ? 0 : (K1 >> 5);
    int T  = T0 + T1;

    float4 Ar[4], Br[4];
    ldg_tile(A0, W0, K0, Cout, 0, row0, col0, M, tid, Ar, Br);

    #pragma unroll 1
    for (int t = 0; t < T; t++) {
        // stage prefetched tile t into smem (tf32-convert here, not inner loop)
        #pragma unroll
        for (int i = 0; i < 4; i++) {
            int lin = tid + i * 256;
            int r = lin >> 3, c4 = (lin & 7) << 2;
            As[r][c4 + 0] = to_tf32(Ar[i].x);
            As[r][c4 + 1] = to_tf32(Ar[i].y);
            As[r][c4 + 2] = to_tf32(Ar[i].z);
            As[r][c4 + 3] = to_tf32(Ar[i].w);
        }
        #pragma unroll
        for (int i = 0; i < 4; i++) {
            int lin = tid + i * 256;
            int bk = lin >> 5, c4 = (lin & 31) << 2;
            Bs[bk][c4 + 0] = to_tf32(Br[i].x);
            Bs[bk][c4 + 1] = to_tf32(Br[i].y);
            Bs[bk][c4 + 2] = to_tf32(Br[i].z);
            Bs[bk][c4 + 3] = to_tf32(Br[i].w);
        }
        __syncthreads();

        // prefetch tile t+1 (LDGs fly under the mma compute below)
        if (t + 1 < T) {
            int tn_ = t + 1;
            const float* A = (tn_ < T0) ? A0 : A1;
            const float* W = (tn_ < T0) ? W0 : W1;
            int K  = (tn_ < T0) ? K0 : K1;
            int kt = (tn_ < T0) ? tn_ * BK : (tn_ - T0) * BK;
            ldg_tile(A, W, K, Cout, kt, row0, col0, M, tid, Ar, Br);
        }

        #pragma unroll
        for (int ks = 0; ks < 4; ks++) {
            int k0 = ks * 8;
            uint32_t af[2][4];
            #pragma unroll
            for (int mt = 0; mt < 2; mt++) {
                int r = wm * 32 + mt * 16 + gid;
                af[mt][0] = __float_as_uint(As[r    ][k0 + tig]);
                af[mt][1] = __float_as_uint(As[r + 8][k0 + tig]);
                af[mt][2] = __float_as_uint(As[r    ][k0 + tig + 4]);
                af[mt][3] = __float_as_uint(As[r + 8][k0 + tig + 4]);
            }
            uint32_t bf[8][2];
            #pragma unroll
            for (int nt = 0; nt < 8; nt++) {
                int c = wn * 64 + nt * 8 + gid;
                bf[nt][0] = __float_as_uint(Bs[k0 + tig    ][c]);
                bf[nt][1] = __float_as_uint(Bs[k0 + tig + 4][c]);
            }
            #pragma unroll
            for (int mt = 0; mt < 2; mt++)
                #pragma unroll
                for (int nt = 0; nt < 8; nt++)
                    mma_tf32(acc[mt][nt], af[mt], bf[nt]);
        }
        __syncthreads();
    }

    float* C = out_ptr(c_sel);
    #pragma unroll
    for (int mt = 0; mt < 2; mt++) {
        #pragma unroll
        for (int half = 0; half < 2; half++) {
            int r = row0 + wm * 32 + mt * 16 + gid + half * 8;
            if (r < M) {
                #pragma unroll
                for (int nt = 0; nt < 8; nt++) {
                    int c = col0 + wn * 64 + nt * 8 + tig * 2;
                    float v0 = acc[mt][nt][half * 2 + 0];
                    float v1 = acc[mt][nt][half * 2 + 1];
                    if (bias) { v0 += bias[c]; v1 += bias[c + 1]; }
                    if (relu) { v0 = fmaxf(v0, 0.f); v1 = fmaxf(v1, 0.f); }
                    *(float2*)&C[(size_t)r * Cout + c] = make_float2(v0, v1);
                }
            }
        }
    }
}

// ---------------------------------------------------------------------------
// Graph segment boundaries via binary search over sorted batch (int32)
// ---------------------------------------------------------------------------
__global__ void gstart_kernel(const int* __restrict__ batch) {
    int g = blockIdx.x * blockDim.x + threadIdx.x;
    if (g > GG) return;
    int lo = 0, hi = NN;
    while (lo < hi) {
        int mid = (lo + hi) >> 1;
        if (batch[mid] < g) lo = mid + 1; else hi = mid;
    }
    g_gstart[g] = lo;
}

// ---------------------------------------------------------------------------
// Pool (mean over graph) + 2-layer MLP head. One 128-thread block per graph.
// h3[n] = g_agg[n] + g_z3[n]   (R5 form: reads the precomputed agg of y3)
// ---------------------------------------------------------------------------
__global__ void pool_head_kernel(const float* __restrict__ W1,
                                 const float* __restrict__ b1,
                                 const float* __restrict__ W2,
                                 const float* __restrict__ b2,
                                 float* __restrict__ out) {
    int g = blockIdx.x;
    int c = threadIdx.x;  // 0..127
    int s = g_gstart[g];
    int e = g_gstart[g + 1];
    const float* agg = (const float*)g_agg4;
    const float* z3  = (const float*)g_z3_4;
    float acc = 0.f;
    for (int n = s; n < e; n++)
        acc += agg[(size_t)n * 128 + c] + z3[(size_t)n * 128 + c];
    float cnt = (float)((e - s) > 1 ? (e - s) : 1);
    __shared__ float p[128];
    __shared__ float t[40];
    p[c] = acc / cnt;
    __syncthreads();
    if (c < 40) {
        float tt = b1[c];
        #pragma unroll 4
        for (int k = 0; k < 128; k++) tt += p[k] * W1[k * 40 + c];
        t[c] = tt;
    }
    __syncthreads();
    if (c < 10) {
        float o = b2[c];
        #pragma unroll
        for (int k = 0; k < 40; k++) o += t[k] * W2[k * 10 + c];
        out[g * 10 + c] = o;
    }
}

// ---------------------------------------------------------------------------
// Launch: ONLY kernel launches.
// ---------------------------------------------------------------------------
extern "C" void kernel_launch(void* const* d_in, const int* in_sizes, int n_in,
                              void* d_out, int out_size) {
    const float* x     = (const float*)d_in[0];
    const int*   ei    = (const int*)d_in[1];
    const int*   batch = (const int*)d_in[2];
    const float* Wr1 = (const float*)d_in[3];
    const float* br1 = (const float*)d_in[4];
    const float* Wo1 = (const float*)d_in[5];
    const float* Wr2 = (const float*)d_in[6];
    const float* br2 = (const float*)d_in[7];
    const float* Wo2 = (const float*)d_in[8];
    const float* Wr3 = (const float*)d_in[9];
    const float* br3 = (const float*)d_in[10];
    const float* Wo3 = (const float*)d_in[11];
    const float* W1  = (const float*)d_in[12];
    const float* b1  = (const float*)d_in[13];
    const float* W2  = (const float*)d_in[14];
    const float* b2  = (const float*)d_in[15];
    float* out = (float*)d_out;

    const int* srcp = ei;
    const int* dstp = ei + EE;

    const int EB = (EE + 255) / 256;
    const int AGGB = (NN * 32 + 255) / 256;
    dim3 g1((NN + 127) / 128, 1);
    dim3 g2((NN + 127) / 128, 2);

    // CSR build
    zero_deg_kernel<<<(NN + 255) / 256, 256>>>();
    count_kernel<<<EB, 256>>>(dstp);
    scan_kernel<<<1, 1024>>>();
    fill_kernel<<<EB, 256>>>(srcp, dstp);
    gstart_kernel<<<1, 1024>>>(batch);

    // Layer 1: agg = A(x); h1 = relu(agg@Wr1 + x@Wo1 + br1)
    aggregate_kernel<<<AGGB, 256>>>(x, 5);
    gemm_tc_kernel<<<g1, 256>>>(x, 0, Wr1, 128, 5, Wo1, 128, br1, 1,
                                NN, 128, 1, nullptr, nullptr, 0);

    // Layer 2: agg = A(h1); h2 = relu(agg@Wr2 + h1@Wo2 + br2)
    aggregate_kernel<<<AGGB, 256>>>(x, 1);
    gemm_tc_kernel<<<g2, 256>>>(x, 0, Wr2, 128, 1, Wo2, 128, br2, 2,
                                NN, 256, 1, nullptr, nullptr, 0);

    // Layer 3 (matmul-first, dual-output): y3 = h2@Wr3; z3 = h2@Wo3 + br3
    gemm_tc_kernel<<<g2, 256>>>(x, 2, Wr3, 256, -1, nullptr, 0, nullptr, 3,
                                NN, 128, 0, Wo3, br3, 4);

    // agg = A(y3), then pool + head
    aggregate_kernel<<<AGGB, 256>>>(x, 3);
    pool_head_kernel<<<GG, 128>>>(W1, b1, W2, b2, out);
}

// round 8
// speedup vs baseline: 1.6825x; 1.0434x over previous
#include <cuda_runtime.h>
#include <cuda_fp16.h>
#include <cstdint>

#define NN 50000
#define EE 1600000
#define GG 512

// ---------------------------------------------------------------------------
// Device scratch (static; no allocations anywhere)
// ---------------------------------------------------------------------------
__device__ int    g_deg[NN];
__device__ int    g_rowptr[NN + 1];
__device__ int    g_fill[NN];
__device__ int    g_col[EE];
__device__ int    g_gstart[GG + 1];
__device__ float4 g_agg4[(size_t)NN * 32];   // [N,128] fp32
__device__ float4 g_h1_4[(size_t)NN * 32];   // [N,128] fp32
__device__ float4 g_h2_4[(size_t)NN * 64];   // [N,256] fp32
__device__ float4 g_y3_4[(size_t)NN * 32];   // [N,128] fp32
__device__ float4 g_z3_4[(size_t)NN * 32];   // [N,128] fp32
// fp16 mirrors of the three tensors that get aggregated (gather at 256B/edge)
__device__ __half2 g_xh [(size_t)NN * 64];   // [N,128] fp16
__device__ __half2 g_h1h[(size_t)NN * 64];
__device__ __half2 g_y3h[(size_t)NN * 64];

__device__ __forceinline__ const float* buf_ptr(int sel, const float* x) {
    switch (sel) {
        case 0: return (const float*)g_agg4;
        case 1: return (const float*)g_h1_4;
        case 2: return (const float*)g_h2_4;
        case 3: return (const float*)g_y3_4;
        case 4: return (const float*)g_z3_4;
        default: return x;
    }
}
__device__ __forceinline__ float* out_ptr(int sel) {
    switch (sel) {
        case 0: return (float*)g_agg4;
        case 1: return (float*)g_h1_4;
        case 2: return (float*)g_h2_4;
        case 3: return (float*)g_y3_4;
        default: return (float*)g_z3_4;
    }
}
__device__ __forceinline__ const __half2* hbuf_ptr(int sel) {
    switch (sel) {
        case 0: return g_xh;
        case 1: return g_h1h;
        default: return g_y3h;
    }
}
__device__ __forceinline__ __half2* hout_ptr(int sel) {
    switch (sel) {
        case 0: return g_xh;
        case 1: return g_h1h;
        default: return g_y3h;
    }
}

// ---------------------------------------------------------------------------
// fp16 mirror of x (one-shot convert; 6.4M elements, 4 per thread)
// ---------------------------------------------------------------------------
__global__ void convert_x_kernel(const float* __restrict__ x) {
    int i = blockIdx.x * blockDim.x + threadIdx.x;   // float4 index
    if (i < NN * 32) {
        float4 v = *(const float4*)&x[i * 4];
        g_xh[i * 2 + 0] = __floats2half2_rn(v.x, v.y);
        g_xh[i * 2 + 1] = __floats2half2_rn(v.z, v.w);
    }
}

// ---------------------------------------------------------------------------
// CSR construction (int32 indices)
// ---------------------------------------------------------------------------
__global__ void zero_deg_kernel() {
    int i = blockIdx.x * blockDim.x + threadIdx.x;
    if (i < NN) g_deg[i] = 0;
}

__global__ void count_kernel(const int* __restrict__ dst) {
    int e = blockIdx.x * blockDim.x + threadIdx.x;
    if (e < EE) {
        int d = dst[e];
        if (d >= 0 && d < NN) atomicAdd(&g_deg[d], 1);
    }
}

__global__ void scan_kernel() {
    __shared__ int wsum[32];
    __shared__ int carry_s;
    int tid = threadIdx.x;
    int lane = tid & 31, wid = tid >> 5;
    if (tid == 0) carry_s = 0;
    __syncthreads();
    for (int base = 0; base < NN; base += 1024) {
        int idx = base + tid;
        int v = (idx < NN) ? g_deg[idx] : 0;
        int sc = v;
        #pragma unroll
        for (int o = 1; o < 32; o <<= 1) {
            int t = __shfl_up_sync(0xFFFFFFFFu, sc, o);
            if (lane >= o) sc += t;
        }
        if (lane == 31) wsum[wid] = sc;
        __syncthreads();
        if (wid == 0) {
            int w = wsum[lane];
            int ws = w;
            #pragma unroll
            for (int o = 1; o < 32; o <<= 1) {
                int t = __shfl_up_sync(0xFFFFFFFFu, ws, o);
                if (lane >= o) ws += t;
            }
            wsum[lane] = ws - w;
        }
        __syncthreads();
        int excl = carry_s + wsum[wid] + sc - v;
        if (idx < NN) {
            g_rowptr[idx] = excl;
            g_fill[idx]   = excl;
        }
        __syncthreads();
        if (tid == 1023) carry_s = excl + v;
        __syncthreads();
    }
    if (threadIdx.x == 0) g_rowptr[NN] = carry_s;
}

__global__ void fill_kernel(const int* __restrict__ src,
                            const int* __restrict__ dst) {
    int e = blockIdx.x * blockDim.x + threadIdx.x;
    if (e < EE) {
        int d = dst[e];
        if (d >= 0 && d < NN) {
            int p = atomicAdd(&g_fill[d], 1);
            g_col[p] = src[e];
        }
    }
}

// ---------------------------------------------------------------------------
// fp16 aggregation: g_agg[n] = sum over in-edges of feat_h[src] (fp32 accum).
// One warp per node; each lane reads 8 bytes (4 halves) per edge.
// ---------------------------------------------------------------------------
__global__ void aggregate_h_kernel(int feat_sel) {
    const __half2* feat = hbuf_ptr(feat_sel);
    int warp = (blockIdx.x * blockDim.x + threadIdx.x) >> 5;
    int lane = threadIdx.x & 31;
    if (warp >= NN) return;
    int s = g_rowptr[warp];
    int e = g_rowptr[warp + 1];
    float4 acc = make_float4(0.f, 0.f, 0.f, 0.f);
    for (int j = s; j < e; j++) {
        int c = g_col[j];
        // 8-byte load: two half2 = 4 features
        uint2 raw = *(const uint2*)&feat[(size_t)c * 64 + lane * 2];
        __half2 ha = *(__half2*)&raw.x;
        __half2 hb = *(__half2*)&raw.y;
        float2 fa = __half22float2(ha);
        float2 fb = __half22float2(hb);
        acc.x += fa.x; acc.y += fa.y; acc.z += fb.x; acc.w += fb.y;
    }
    g_agg4[(size_t)warp * 32 + lane] = acc;
}

// ---------------------------------------------------------------------------
// tf32 tensor-core GEMM with register-prefetch double buffering.
// 128x128 tile, BK=32, 8 warps (4x2), warp tile 32x64 via m16n8k8 tf32 mma.
// Dual-input (A0@W0 + A1@W1); dual-output (Wb/biasb/cb on blockIdx.y==1).
// Optional fp16 mirror write of C (hc_sel >= 0; primary output only).
// ---------------------------------------------------------------------------
__device__ __forceinline__ float to_tf32(float x) {
    float r;
    asm("cvt.rna.tf32.f32 %0, %1;" : "=f"(r) : "f"(x));
    return r;
}
__device__ __forceinline__ void mma_tf32(float* c, const uint32_t* a,
                                         const uint32_t* b) {
    asm volatile(
        "mma.sync.aligned.m16n8k8.row.col.f32.tf32.tf32.f32 "
        "{%0,%1,%2,%3}, {%4,%5,%6,%7}, {%8,%9}, {%0,%1,%2,%3};"
        : "+f"(c[0]), "+f"(c[1]), "+f"(c[2]), "+f"(c[3])
        : "r"(a[0]), "r"(a[1]), "r"(a[2]), "r"(a[3]), "r"(b[0]), "r"(b[1]));
}

#define BM 128
#define BN 128
#define BK 32

__device__ __forceinline__ void ldg_tile(
    const float* __restrict__ A, const float* __restrict__ W,
    int K, int Cout, int kt, int row0, int col0, int M, int tid,
    float4* Ar, float4* Br) {
    #pragma unroll
    for (int i = 0; i < 4; i++) {
        int lin = tid + i * 256;
        int r = lin >> 3, c4 = (lin & 7) << 2;
        int gr = row0 + r;
        Ar[i] = (gr < M) ? *(const float4*)&A[(size_t)gr * K + kt + c4]
                         : make_float4(0.f, 0.f, 0.f, 0.f);
    }
    #pragma unroll
    for (int i = 0; i < 4; i++) {
        int lin = tid + i * 256;
        int bk = lin >> 5, c4 = (lin & 31) << 2;
        Br[i] = *(const float4*)&W[(size_t)(kt + bk) * Cout + col0 + c4];
    }
}

__global__ void __launch_bounds__(256, 2)
gemm_tc_kernel(const float* __restrict__ x,
               int a0_sel, const float* __restrict__ W0, int K0,
               int a1_sel, const float* __restrict__ W1, int K1,
               const float* __restrict__ bias, int c_sel,
               int M, int Cout, int relu,
               const float* __restrict__ Wb, const float* __restrict__ biasb,
               int cb_sel, int hc_sel) {
    __shared__ float As[BM][BK + 4];
    __shared__ float Bs[BK][BN + 8];

    int tid  = threadIdx.x;
    int wid  = tid >> 5, lane = tid & 31;
    int gid  = lane >> 2, tig = lane & 3;
    int wm   = wid & 3,  wn  = wid >> 2;
    int row0 = blockIdx.x * BM;
    int col0;
    if (Wb != nullptr) {             // dual-output: blockIdx.y picks W/bias/C
        col0 = 0;
        if (blockIdx.y == 1) { W0 = Wb; bias = biasb; c_sel = cb_sel; hc_sel = -1; }
    } else {
        col0 = blockIdx.y * BN;
    }

    float acc[2][8][4];
    #pragma unroll
    for (int i = 0; i < 2; i++)
        #pragma unroll
        for (int j = 0; j < 8; j++)
            #pragma unroll
            for (int k = 0; k < 4; k++) acc[i][j][k] = 0.f;

    const float* A0 = buf_ptr(a0_sel, x);
    const float* A1 = (a1_sel < 0) ? nullptr : buf_ptr(a1_sel, x);
    int T0 = K0 >> 5;
    int T1 = (a1_sel < 0) ? 0 : (K1 >> 5);
    int T  = T0 + T1;

    float4 Ar[4], Br[4];
    ldg_tile(A0, W0, K0, Cout, 0, row0, col0, M, tid, Ar, Br);

    #pragma unroll 1
    for (int t = 0; t < T; t++) {
        #pragma unroll
        for (int i = 0; i < 4; i++) {
            int lin = tid + i * 256;
            int r = lin >> 3, c4 = (lin & 7) << 2;
            As[r][c4 + 0] = to_tf32(Ar[i].x);
            As[r][c4 + 1] = to_tf32(Ar[i].y);
            As[r][c4 + 2] = to_tf32(Ar[i].z);
            As[r][c4 + 3] = to_tf32(Ar[i].w);
        }
        #pragma unroll
        for (int i = 0; i < 4; i++) {
            int lin = tid + i * 256;
            int bk = lin >> 5, c4 = (lin & 31) << 2;
            Bs[bk][c4 + 0] = to_tf32(Br[i].x);
            Bs[bk][c4 + 1] = to_tf32(Br[i].y);
            Bs[bk][c4 + 2] = to_tf32(Br[i].z);
            Bs[bk][c4 + 3] = to_tf32(Br[i].w);
        }
        __syncthreads();

        if (t + 1 < T) {
            int tn_ = t + 1;
            const float* A = (tn_ < T0) ? A0 : A1;
            const float* W = (tn_ < T0) ? W0 : W1;
            int K  = (tn_ < T0) ? K0 : K1;
            int kt = (tn_ < T0) ? tn_ * BK : (tn_ - T0) * BK;
            ldg_tile(A, W, K, Cout, kt, row0, col0, M, tid, Ar, Br);
        }

        #pragma unroll
        for (int ks = 0; ks < 4; ks++) {
            int k0 = ks * 8;
            uint32_t af[2][4];
            #pragma unroll
            for (int mt = 0; mt < 2; mt++) {
                int r = wm * 32 + mt * 16 + gid;
                af[mt][0] = __float_as_uint(As[r    ][k0 + tig]);
                af[mt][1] = __float_as_uint(As[r + 8][k0 + tig]);
                af[mt][2] = __float_as_uint(As[r    ][k0 + tig + 4]);
                af[mt][3] = __float_as_uint(As[r + 8][k0 + tig + 4]);
            }
            uint32_t bf[8][2];
            #pragma unroll
            for (int nt = 0; nt < 8; nt++) {
                int c = wn * 64 + nt * 8 + gid;
                bf[nt][0] = __float_as_uint(Bs[k0 + tig    ][c]);
                bf[nt][1] = __float_as_uint(Bs[k0 + tig + 4][c]);
            }
            #pragma unroll
            for (int mt = 0; mt < 2; mt++)
                #pragma unroll
                for (int nt = 0; nt < 8; nt++)
                    mma_tf32(acc[mt][nt], af[mt], bf[nt]);
        }
        __syncthreads();
    }

    float* C = out_ptr(c_sel);
    __half2* Ch = (hc_sel >= 0) ? hout_ptr(hc_sel) : nullptr;
    #pragma unroll
    for (int mt = 0; mt < 2; mt++) {
        #pragma unroll
        for (int half_ = 0; half_ < 2; half_++) {
            int r = row0 + wm * 32 + mt * 16 + gid + half_ * 8;
            if (r < M) {
                #pragma unroll
                for (int nt = 0; nt < 8; nt++) {
                    int c = col0 + wn * 64 + nt * 8 + tig * 2;
                    float v0 = acc[mt][nt][half_ * 2 + 0];
                    float v1 = acc[mt][nt][half_ * 2 + 1];
                    if (bias) { v0 += bias[c]; v1 += bias[c + 1]; }
                    if (relu) { v0 = fmaxf(v0, 0.f); v1 = fmaxf(v1, 0.f); }
                    *(float2*)&C[(size_t)r * Cout + c] = make_float2(v0, v1);
                    if (Ch) Ch[((size_t)r * Cout + c) >> 1] =
                        __floats2half2_rn(v0, v1);
                }
            }
        }
    }
}

// ---------------------------------------------------------------------------
// Graph segment boundaries via binary search over sorted batch (int32)
// ---------------------------------------------------------------------------
__global__ void gstart_kernel(const int* __restrict__ batch) {
    int g = blockIdx.x * blockDim.x + threadIdx.x;
    if (g > GG) return;
    int lo = 0, hi = NN;
    while (lo < hi) {
        int mid = (lo + hi) >> 1;
        if (batch[mid] < g) lo = mid + 1; else hi = mid;
    }
    g_gstart[g] = lo;
}

// ---------------------------------------------------------------------------
// Pool (mean over graph) + 2-layer MLP head. One 128-thread block per graph.
// h3[n] = g_agg[n] + g_z3[n]
// ---------------------------------------------------------------------------
__global__ void pool_head_kernel(const float* __restrict__ W1,
                                 const float* __restrict__ b1,
                                 const float* __restrict__ W2,
                                 const float* __restrict__ b2,
                                 float* __restrict__ out) {
    int g = blockIdx.x;
    int c = threadIdx.x;  // 0..127
    int s = g_gstart[g];
    int e = g_gstart[g + 1];
    const float* agg = (const float*)g_agg4;
    const float* z3  = (const float*)g_z3_4;
    float acc = 0.f;
    for (int n = s; n < e; n++)
        acc += agg[(size_t)n * 128 + c] + z3[(size_t)n * 128 + c];
    float cnt = (float)((e - s) > 1 ? (e - s) : 1);
    __shared__ float p[128];
    __shared__ float t[40];
    p[c] = acc / cnt;
    __syncthreads();
    if (c < 40) {
        float tt = b1[c];
        #pragma unroll 4
        for (int k = 0; k < 128; k++) tt += p[k] * W1[k * 40 + c];
        t[c] = tt;
    }
    __syncthreads();
    if (c < 10) {
        float o = b2[c];
        #pragma unroll
        for (int k = 0; k < 40; k++) o += t[k] * W2[k * 10 + c];
        out[g * 10 + c] = o;
    }
}

// ---------------------------------------------------------------------------
// Launch: ONLY kernel launches.
// ---------------------------------------------------------------------------
extern "C" void kernel_launch(void* const* d_in, const int* in_sizes, int n_in,
                              void* d_out, int out_size) {
    const float* x     = (const float*)d_in[0];
    const int*   ei    = (const int*)d_in[1];
    const int*   batch = (const int*)d_in[2];
    const float* Wr1 = (const float*)d_in[3];
    const float* br1 = (const float*)d_in[4];
    const float* Wo1 = (const float*)d_in[5];
    const float* Wr2 = (const float*)d_in[6];
    const float* br2 = (const float*)d_in[7];
    const float* Wo2 = (const float*)d_in[8];
    const float* Wr3 = (const float*)d_in[9];
    const float* br3 = (const float*)d_in[10];
    const float* Wo3 = (const float*)d_in[11];
    const float* W1  = (const float*)d_in[12];
    const float* b1  = (const float*)d_in[13];
    const float* W2  = (const float*)d_in[14];
    const float* b2  = (const float*)d_in[15];
    float* out = (float*)d_out;

    const int* srcp = ei;
    const int* dstp = ei + EE;

    const int EB = (EE + 255) / 256;
    const int AGGB = (NN * 32 + 255) / 256;
    dim3 g1((NN + 127) / 128, 1);
    dim3 g2((NN + 127) / 128, 2);

    // CSR build + x fp16 mirror
    zero_deg_kernel<<<(NN + 255) / 256, 256>>>();
    convert_x_kernel<<<(NN * 32 + 255) / 256, 256>>>(x);
    count_kernel<<<EB, 256>>>(dstp);
    scan_kernel<<<1, 1024>>>();
    fill_kernel<<<EB, 256>>>(srcp, dstp);
    gstart_kernel<<<1, 1024>>>(batch);

    // Layer 1: agg = A(x_h); h1 = relu(agg@Wr1 + x@Wo1 + br1)  (+h1 fp16 mirror)
    aggregate_h_kernel<<<AGGB, 256>>>(0);
    gemm_tc_kernel<<<g1, 256>>>(x, 0, Wr1, 128, 5, Wo1, 128, br1, 1,
                                NN, 128, 1, nullptr, nullptr, 0, 1);

    // Layer 2: agg = A(h1_h); h2 = relu(agg@Wr2 + h1@Wo2 + br2)
    aggregate_h_kernel<<<AGGB, 256>>>(1);
    gemm_tc_kernel<<<g2, 256>>>(x, 0, Wr2, 128, 1, Wo2, 128, br2, 2,
                                NN, 256, 1, nullptr, nullptr, 0, -1);

    // Layer 3 (matmul-first, dual-output): y3 = h2@Wr3 (+fp16 mirror);
    // z3 = h2@Wo3 + br3
    gemm_tc_kernel<<<g2, 256>>>(x, 2, Wr3, 256, -1, nullptr, 0, nullptr, 3,
                                NN, 128, 0, Wo3, br3, 4, 2);

    // agg = A(y3_h), then pool + head
    aggregate_h_kernel<<<AGGB, 256>>>(2);
    pool_head_kernel<<<GG, 128>>>(W1, b1, W2, b2, out);
}

// round 9
// speedup vs baseline: 1.8333x; 1.0896x over previous
#include <cuda_runtime.h>
#include <cuda_fp16.h>
#include <cstdint>

#define NN 50000
#define EE 1600000
#define GG 512
#define SCAN_BLKS ((NN + 1023) / 1024)   // 49

// ---------------------------------------------------------------------------
// Device scratch (static; no allocations anywhere)
// ---------------------------------------------------------------------------
__device__ int    g_deg[NN];
__device__ int    g_rowptr[NN + 1];
__device__ int    g_fill[NN];
__device__ int    g_col[EE];
__device__ int    g_gstart[GG + 1];
__device__ int    g_bsum[SCAN_BLKS];
__device__ int    g_boff[SCAN_BLKS];
__device__ float4 g_agg4[(size_t)NN * 32];   // [N,128] fp32
__device__ float4 g_h1_4[(size_t)NN * 32];   // [N,128] fp32
__device__ float4 g_h2_4[(size_t)NN * 64];   // [N,256] fp32
__device__ float4 g_y3_4[(size_t)NN * 32];   // [N,128] fp32
__device__ float4 g_z3_4[(size_t)NN * 32];   // [N,128] fp32
// fp16 mirrors of the three tensors that get aggregated (gather at 256B/edge)
__device__ __half2 g_xh [(size_t)NN * 64];   // [N,128] fp16
__device__ __half2 g_h1h[(size_t)NN * 64];
__device__ __half2 g_y3h[(size_t)NN * 64];

__device__ __forceinline__ const float* buf_ptr(int sel, const float* x) {
    switch (sel) {
        case 0: return (const float*)g_agg4;
        case 1: return (const float*)g_h1_4;
        case 2: return (const float*)g_h2_4;
        case 3: return (const float*)g_y3_4;
        case 4: return (const float*)g_z3_4;
        default: return x;
    }
}
__device__ __forceinline__ float* out_ptr(int sel) {
    switch (sel) {
        case 0: return (float*)g_agg4;
        case 1: return (float*)g_h1_4;
        case 2: return (float*)g_h2_4;
        case 3: return (float*)g_y3_4;
        default: return (float*)g_z3_4;
    }
}
__device__ __forceinline__ const __half2* hbuf_ptr(int sel) {
    switch (sel) {
        case 0: return g_xh;
        case 1: return g_h1h;
        default: return g_y3h;
    }
}
__device__ __forceinline__ __half2* hout_ptr(int sel) {
    switch (sel) {
        case 0: return g_xh;
        case 1: return g_h1h;
        default: return g_y3h;
    }
}

// ---------------------------------------------------------------------------
// fp16 mirror of x (one-shot convert)
// ---------------------------------------------------------------------------
__global__ void convert_x_kernel(const float* __restrict__ x) {
    int i = blockIdx.x * blockDim.x + threadIdx.x;   // float4 index
    if (i < NN * 32) {
        float4 v = *(const float4*)&x[i * 4];
        g_xh[i * 2 + 0] = __floats2half2_rn(v.x, v.y);
        g_xh[i * 2 + 1] = __floats2half2_rn(v.z, v.w);
    }
}

// ---------------------------------------------------------------------------
// CSR construction (int32 indices)
// ---------------------------------------------------------------------------
__global__ void zero_deg_kernel() {
    int i = blockIdx.x * blockDim.x + threadIdx.x;
    if (i < NN) g_deg[i] = 0;
}

__global__ void count_kernel(const int* __restrict__ dst) {
    int e = blockIdx.x * blockDim.x + threadIdx.x;
    if (e < EE) {
        int d = dst[e];
        if (d >= 0 && d < NN) atomicAdd(&g_deg[d], 1);
    }
}

// --- 3-phase parallel exclusive scan of g_deg -> g_rowptr, g_fill ----------
__global__ void block_reduce_kernel() {
    __shared__ int wsum[32];
    int tid = threadIdx.x, lane = tid & 31, wid = tid >> 5;
    int idx = blockIdx.x * 1024 + tid;
    int v = (idx < NN) ? g_deg[idx] : 0;
    int s = v;
    #pragma unroll
    for (int o = 16; o > 0; o >>= 1) s += __shfl_down_sync(0xFFFFFFFFu, s, o);
    if (lane == 0) wsum[wid] = s;
    __syncthreads();
    if (wid == 0) {
        int t = wsum[lane];
        #pragma unroll
        for (int o = 16; o > 0; o >>= 1) t += __shfl_down_sync(0xFFFFFFFFu, t, o);
        if (lane == 0) g_bsum[blockIdx.x] = t;
    }
}

__global__ void scan_bsums_kernel() {
    // single block of 64 threads; SCAN_BLKS=49 <= 64
    int tid = threadIdx.x;
    int lane = tid & 31, wid = tid >> 5;
    __shared__ int w0sum;
    int v = (tid < SCAN_BLKS) ? g_bsum[tid] : 0;
    int sc = v;
    #pragma unroll
    for (int o = 1; o < 32; o <<= 1) {
        int t = __shfl_up_sync(0xFFFFFFFFu, sc, o);
        if (lane >= o) sc += t;
    }
    if (tid == 31) w0sum = sc;
    __syncthreads();
    int excl = sc - v + (wid ? w0sum : 0);
    if (tid < SCAN_BLKS) g_boff[tid] = excl;
    if (tid == SCAN_BLKS - 1) g_rowptr[NN] = excl + v;
}

__global__ void block_scan_kernel() {
    __shared__ int wsum[32];
    int tid = threadIdx.x, lane = tid & 31, wid = tid >> 5;
    int idx = blockIdx.x * 1024 + tid;
    int v = (idx < NN) ? g_deg[idx] : 0;
    int sc = v;
    #pragma unroll
    for (int o = 1; o < 32; o <<= 1) {
        int t = __shfl_up_sync(0xFFFFFFFFu, sc, o);
        if (lane >= o) sc += t;
    }
    if (lane == 31) wsum[wid] = sc;
    __syncthreads();
    if (wid == 0) {
        int w = wsum[lane];
        int ws = w;
        #pragma unroll
        for (int o = 1; o < 32; o <<= 1) {
            int t = __shfl_up_sync(0xFFFFFFFFu, ws, o);
            if (lane >= o) ws += t;
        }
        wsum[lane] = ws - w;
    }
    __syncthreads();
    if (idx < NN) {
        int excl = g_boff[blockIdx.x] + wsum[wid] + sc - v;
        g_rowptr[idx] = excl;
        g_fill[idx]   = excl;
    }
}

__global__ void fill_kernel(const int* __restrict__ src,
                            const int* __restrict__ dst) {
    int e = blockIdx.x * blockDim.x + threadIdx.x;
    if (e < EE) {
        int d = dst[e];
        if (d >= 0 && d < NN) {
            int p = atomicAdd(&g_fill[d], 1);
            g_col[p] = src[e];
        }
    }
}

// ---------------------------------------------------------------------------
// fp16 aggregation: g_agg[n] = sum over in-edges of feat_h[src] (fp32 accum).
// ---------------------------------------------------------------------------
__global__ void aggregate_h_kernel(int feat_sel) {
    const __half2* feat = hbuf_ptr(feat_sel);
    int warp = (blockIdx.x * blockDim.x + threadIdx.x) >> 5;
    int lane = threadIdx.x & 31;
    if (warp >= NN) return;
    int s = g_rowptr[warp];
    int e = g_rowptr[warp + 1];
    float4 acc = make_float4(0.f, 0.f, 0.f, 0.f);
    for (int j = s; j < e; j++) {
        int c = g_col[j];
        uint2 raw = *(const uint2*)&feat[(size_t)c * 64 + lane * 2];
        __half2 ha = *(__half2*)&raw.x;
        __half2 hb = *(__half2*)&raw.y;
        float2 fa = __half22float2(ha);
        float2 fb = __half22float2(hb);
        acc.x += fa.x; acc.y += fa.y; acc.z += fb.x; acc.w += fb.y;
    }
    g_agg4[(size_t)warp * 32 + lane] = acc;
}

// ---------------------------------------------------------------------------
// tf32 tensor-core GEMM with register-prefetch double buffering.
// ---------------------------------------------------------------------------
__device__ __forceinline__ float to_tf32(float x) {
    float r;
    asm("cvt.rna.tf32.f32 %0, %1;" : "=f"(r) : "f"(x));
    return r;
}
__device__ __forceinline__ void mma_tf32(float* c, const uint32_t* a,
                                         const uint32_t* b) {
    asm volatile(
        "mma.sync.aligned.m16n8k8.row.col.f32.tf32.tf32.f32 "
        "{%0,%1,%2,%3}, {%4,%5,%6,%7}, {%8,%9}, {%0,%1,%2,%3};"
        : "+f"(c[0]), "+f"(c[1]), "+f"(c[2]), "+f"(c[3])
        : "r"(a[0]), "r"(a[1]), "r"(a[2]), "r"(a[3]), "r"(b[0]), "r"(b[1]));
}

#define BM 128
#define BN 128
#define BK 32

__device__ __forceinline__ void ldg_tile(
    const float* __restrict__ A, const float* __restrict__ W,
    int K, int Cout, int kt, int row0, int col0, int M, int tid,
    float4* Ar, float4* Br) {
    #pragma unroll
    for (int i = 0; i < 4; i++) {
        int lin = tid + i * 256;
        int r = lin >> 3, c4 = (lin & 7) << 2;
        int gr = row0 + r;
        Ar[i] = (gr < M) ? *(const float4*)&A[(size_t)gr * K + kt + c4]
                         : make_float4(0.f, 0.f, 0.f, 0.f);
    }
    #pragma unroll
    for (int i = 0; i < 4; i++) {
        int lin = tid + i * 256;
        int bk = lin >> 5, c4 = (lin & 31) << 2;
        Br[i] = *(const float4*)&W[(size_t)(kt + bk) * Cout + col0 + c4];
    }
}

__global__ void __launch_bounds__(256, 2)
gemm_tc_kernel(const float* __restrict__ x,
               int a0_sel, const float* __restrict__ W0, int K0,
               int a1_sel, const float* __restrict__ W1, int K1,
               const float* __restrict__ bias, int c_sel,
               int M, int Cout, int relu,
               const float* __restrict__ Wb, const float* __restrict__ biasb,
               int cb_sel, int hc_sel) {
    __shared__ float As[BM][BK + 4];
    __shared__ float Bs[BK][BN + 8];

    int tid  = threadIdx.x;
    int wid  = tid >> 5, lane = tid & 31;
    int gid  = lane >> 2, tig = lane & 3;
    int wm   = wid & 3,  wn  = wid >> 2;
    int row0 = blockIdx.x * BM;
    int col0;
    if (Wb != nullptr) {             // dual-output: blockIdx.y picks W/bias/C
        col0 = 0;
        if (blockIdx.y == 1) { W0 = Wb; bias = biasb; c_sel = cb_sel; hc_sel = -1; }
    } else {
        col0 = blockIdx.y * BN;
    }

    float acc[2][8][4];
    #pragma unroll
    for (int i = 0; i < 2; i++)
        #pragma unroll
        for (int j = 0; j < 8; j++)
            #pragma unroll
            for (int k = 0; k < 4; k++) acc[i][j][k] = 0.f;

    const float* A0 = buf_ptr(a0_sel, x);
    const float* A1 = (a1_sel < 0) ? nullptr : buf_ptr(a1_sel, x);
    int T0 = K0 >> 5;
    int T1 = (a1_sel < 0) ? 0 : (K1 >> 5);
    int T  = T0 + T1;

    float4 Ar[4], Br[4];
    ldg_tile(A0, W0, K0, Cout, 0, row0, col0, M, tid, Ar, Br);

    #pragma unroll 1
    for (int t = 0; t < T; t++) {
        #pragma unroll
        for (int i = 0; i < 4; i++) {
            int lin = tid + i * 256;
            int r = lin >> 3, c4 = (lin & 7) << 2;
            As[r][c4 + 0] = to_tf32(Ar[i].x);
            As[r][c4 + 1] = to_tf32(Ar[i].y);
            As[r][c4 + 2] = to_tf32(Ar[i].z);
            As[r][c4 + 3] = to_tf32(Ar[i].w);
        }
        #pragma unroll
        for (int i = 0; i < 4; i++) {
            int lin = tid + i * 256;
            int bk = lin >> 5, c4 = (lin & 31) << 2;
            Bs[bk][c4 + 0] = to_tf32(Br[i].x);
            Bs[bk][c4 + 1] = to_tf32(Br[i].y);
            Bs[bk][c4 + 2] = to_tf32(Br[i].z);
            Bs[bk][c4 + 3] = to_tf32(Br[i].w);
        }
        __syncthreads();

        if (t + 1 < T) {
            int tn_ = t + 1;
            const float* A = (tn_ < T0) ? A0 : A1;
            const float* W = (tn_ < T0) ? W0 : W1;
            int K  = (tn_ < T0) ? K0 : K1;
            int kt = (tn_ < T0) ? tn_ * BK : (tn_ - T0) * BK;
            ldg_tile(A, W, K, Cout, kt, row0, col0, M, tid, Ar, Br);
        }

        #pragma unroll
        for (int ks = 0; ks < 4; ks++) {
            int k0 = ks * 8;
            uint32_t af[2][4];
            #pragma unroll
            for (int mt = 0; mt < 2; mt++) {
                int r = wm * 32 + mt * 16 + gid;
                af[mt][0] = __float_as_uint(As[r    ][k0 + tig]);
                af[mt][1] = __float_as_uint(As[r + 8][k0 + tig]);
                af[mt][2] = __float_as_uint(As[r    ][k0 + tig + 4]);
                af[mt][3] = __float_as_uint(As[r + 8][k0 + tig + 4]);
            }
            uint32_t bf[8][2];
            #pragma unroll
            for (int nt = 0; nt < 8; nt++) {
                int c = wn * 64 + nt * 8 + gid;
                bf[nt][0] = __float_as_uint(Bs[k0 + tig    ][c]);
                bf[nt][1] = __float_as_uint(Bs[k0 + tig + 4][c]);
            }
            #pragma unroll
            for (int mt = 0; mt < 2; mt++)
                #pragma unroll
                for (int nt = 0; nt < 8; nt++)
                    mma_tf32(acc[mt][nt], af[mt], bf[nt]);
        }
        __syncthreads();
    }

    float* C = out_ptr(c_sel);
    __half2* Ch = (hc_sel >= 0) ? hout_ptr(hc_sel) : nullptr;
    #pragma unroll
    for (int mt = 0; mt < 2; mt++) {
        #pragma unroll
        for (int half_ = 0; half_ < 2; half_++) {
            int r = row0 + wm * 32 + mt * 16 + gid + half_ * 8;
            if (r < M) {
                #pragma unroll
                for (int nt = 0; nt < 8; nt++) {
                    int c = col0 + wn * 64 + nt * 8 + tig * 2;
                    float v0 = acc[mt][nt][half_ * 2 + 0];
                    float v1 = acc[mt][nt][half_ * 2 + 1];
                    if (bias) { v0 += bias[c]; v1 += bias[c + 1]; }
                    if (relu) { v0 = fmaxf(v0, 0.f); v1 = fmaxf(v1, 0.f); }
                    *(float2*)&C[(size_t)r * Cout + c] = make_float2(v0, v1);
                    if (Ch) Ch[((size_t)r * Cout + c) >> 1] =
                        __floats2half2_rn(v0, v1);
                }
            }
        }
    }
}

// ---------------------------------------------------------------------------
// Graph segment boundaries via binary search over sorted batch (int32)
// ---------------------------------------------------------------------------
__global__ void gstart_kernel(const int* __restrict__ batch) {
    int g = blockIdx.x * blockDim.x + threadIdx.x;
    if (g > GG) return;
    int lo = 0, hi = NN;
    while (lo < hi) {
        int mid = (lo + hi) >> 1;
        if (batch[mid] < g) lo = mid + 1; else hi = mid;
    }
    g_gstart[g] = lo;
}

// ---------------------------------------------------------------------------
// Pool (mean over graph) + 2-layer MLP head. One 128-thread block per graph.
// ---------------------------------------------------------------------------
__global__ void pool_head_kernel(const float* __restrict__ W1,
                                 const float* __restrict__ b1,
                                 const float* __restrict__ W2,
                                 const float* __restrict__ b2,
                                 float* __restrict__ out) {
    int g = blockIdx.x;
    int c = threadIdx.x;  // 0..127
    int s = g_gstart[g];
    int e = g_gstart[g + 1];
    const float* agg = (const float*)g_agg4;
    const float* z3  = (const float*)g_z3_4;
    float acc = 0.f;
    for (int n = s; n < e; n++)
        acc += agg[(size_t)n * 128 + c] + z3[(size_t)n * 128 + c];
    float cnt = (float)((e - s) > 1 ? (e - s) : 1);
    __shared__ float p[128];
    __shared__ float t[40];
    p[c] = acc / cnt;
    __syncthreads();
    if (c < 40) {
        float tt = b1[c];
        #pragma unroll 4
        for (int k = 0; k < 128; k++) tt += p[k] * W1[k * 40 + c];
        t[c] = tt;
    }
    __syncthreads();
    if (c < 10) {
        float o = b2[c];
        #pragma unroll
        for (int k = 0; k < 40; k++) o += t[k] * W2[k * 10 + c];
        out[g * 10 + c] = o;
    }
}

// ---------------------------------------------------------------------------
// Launch: ONLY kernel launches.
// ---------------------------------------------------------------------------
extern "C" void kernel_launch(void* const* d_in, const int* in_sizes, int n_in,
                              void* d_out, int out_size) {
    const float* x     = (const float*)d_in[0];
    const int*   ei    = (const int*)d_in[1];
    const int*   batch = (const int*)d_in[2];
    const float* Wr1 = (const float*)d_in[3];
    const float* br1 = (const float*)d_in[4];
    const float* Wo1 = (const float*)d_in[5];
    const float* Wr2 = (const float*)d_in[6];
    const float* br2 = (const float*)d_in[7];
    const float* Wo2 = (const float*)d_in[8];
    const float* Wr3 = (const float*)d_in[9];
    const float* br3 = (const float*)d_in[10];
    const float* Wo3 = (const float*)d_in[11];
    const float* W1  = (const float*)d_in[12];
    const float* b1  = (const float*)d_in[13];
    const float* W2  = (const float*)d_in[14];
    const float* b2  = (const float*)d_in[15];
    float* out = (float*)d_out;

    const int* srcp = ei;
    const int* dstp = ei + EE;

    const int EB = (EE + 255) / 256;
    const int AGGB = (NN * 32 + 255) / 256;
    dim3 g1((NN + 127) / 128, 1);
    dim3 g2((NN + 127) / 128, 2);

    // CSR build + x fp16 mirror (scan parallelized: reduce/scan/scan)
    zero_deg_kernel<<<(NN + 255) / 256, 256>>>();
    convert_x_kernel<<<(NN * 32 + 255) / 256, 256>>>(x);
    count_kernel<<<EB, 256>>>(dstp);
    block_reduce_kernel<<<SCAN_BLKS, 1024>>>();
    scan_bsums_kernel<<<1, 64>>>();
    block_scan_kernel<<<SCAN_BLKS, 1024>>>();
    fill_kernel<<<EB, 256>>>(srcp, dstp);
    gstart_kernel<<<1, 1024>>>(batch);

    // Layer 1: agg = A(x_h); h1 = relu(agg@Wr1 + x@Wo1 + br1)  (+h1 fp16 mirror)
    aggregate_h_kernel<<<AGGB, 256>>>(0);
    gemm_tc_kernel<<<g1, 256>>>(x, 0, Wr1, 128, 5, Wo1, 128, br1, 1,
                                NN, 128, 1, nullptr, nullptr, 0, 1);

    // Layer 2: agg = A(h1_h); h2 = relu(agg@Wr2 + h1@Wo2 + br2)
    aggregate_h_kernel<<<AGGB, 256>>>(1);
    gemm_tc_kernel<<<g2, 256>>>(x, 0, Wr2, 128, 1, Wo2, 128, br2, 2,
                                NN, 256, 1, nullptr, nullptr, 0, -1);

    // Layer 3 (matmul-first, dual-output): y3 = h2@Wr3 (+fp16 mirror);
    // z3 = h2@Wo3 + br3
    gemm_tc_kernel<<<g2, 256>>>(x, 2, Wr3, 256, -1, nullptr, 0, nullptr, 3,
                                NN, 128, 0, Wo3, br3, 4, 2);

    // agg = A(y3_h), then pool + head
    aggregate_h_kernel<<<AGGB, 256>>>(2);
    pool_head_kernel<<<GG, 128>>>(W1, b1, W2, b2, out);
}